// round 8
// baseline (speedup 1.0000x reference)
#include <cuda_runtime.h>

#define NN 50000
#define NE 800000
#define ENC 64
#define OUTD 5

// ---------------- scratch (static __device__ — no allocations allowed) ----------------
__device__ float g_h0[NN * ENC];
__device__ float g_hA[NN * ENC];
__device__ float g_hB[NN * ENC];
__device__ float g_xl[NN * ENC];
__device__ float g_xr[NN * ENC];
__device__ float g_s[NE];
__device__ int   g_counts[NN];
__device__ int   g_rowptr[NN + 1];
__device__ int   g_offs[NN];
__device__ int   g_eids[NE];
__device__ float g_Weff[6 * 4 * ENC];   // per (stack,round): W_edge @ We  [4,64]
__device__ float g_beff[6 * ENC];       // per (stack,round): b_edge @ We  [64]

// ---------------- packed f32x2 helpers (sm_103a FFMA2) ----------------
__device__ __forceinline__ unsigned long long pack2(float h) {
    unsigned long long r;
    asm("mov.b64 %0, {%1, %1};" : "=l"(r) : "f"(h));
    return r;
}
__device__ __forceinline__ void fma2(unsigned long long& acc, unsigned long long w,
                                     unsigned long long h) {
    asm("fma.rn.f32x2 %0, %1, %2, %0;" : "+l"(acc) : "l"(w), "l"(h));
}

// ---------------- CSR build ----------------
__global__ void k_zero_counts() {
    int i = blockIdx.x * blockDim.x + threadIdx.x;
    if (i < NN) g_counts[i] = 0;
}

__global__ void k_count(const int* __restrict__ dst) {
    int e = blockIdx.x * blockDim.x + threadIdx.x;
    if (e < NE) atomicAdd(&g_counts[dst[e]], 1);
}

// single block, 1024 threads: exclusive scan of counts -> rowptr (+ copy to offs)
__global__ void k_scan() {
    __shared__ int swarp[32];
    int tid = threadIdx.x, lane = tid & 31, wid = tid >> 5;
    int base = 0;
    for (int start = 0; start < NN; start += 1024) {
        int i = start + tid;
        int c = (i < NN) ? g_counts[i] : 0;
        int v = c;
#pragma unroll
        for (int d = 1; d < 32; d <<= 1) {
            int t = __shfl_up_sync(0xffffffffu, v, d);
            if (lane >= d) v += t;
        }
        if (lane == 31) swarp[wid] = v;
        __syncthreads();
        if (wid == 0) {
            int wv = swarp[lane];
#pragma unroll
            for (int d = 1; d < 32; d <<= 1) {
                int t = __shfl_up_sync(0xffffffffu, wv, d);
                if (lane >= d) wv += t;
            }
            swarp[lane] = wv;
        }
        __syncthreads();
        int prefix = (wid == 0) ? 0 : swarp[wid - 1];
        int excl = base + prefix + v - c;
        if (i < NN) { g_rowptr[i] = excl; g_offs[i] = excl; }
        int tot = swarp[31];
        __syncthreads();   // protect swarp before next iteration overwrites
        base += tot;
    }
    if (tid == 0) g_rowptr[NN] = base;
}

__global__ void k_scatter(const int* __restrict__ dst) {
    int e = blockIdx.x * blockDim.x + threadIdx.x;
    if (e < NE) {
        int p = atomicAdd(&g_offs[dst[e]], 1);
        g_eids[p] = e;
    }
}

// ---------------- edge-weight folding: Weff = W_edge @ We, beff = b_edge @ We ----------------
__global__ void k_weff(const float* __restrict__ W_edge, const float* __restrict__ b_edge,
                       const float* __restrict__ aWe, const float* __restrict__ cWe) {
    int b = blockIdx.x;          // 0..5 : stack*3 + round
    int k = threadIdx.x;         // 0..63
    const float* We = (b < 3) ? (aWe + b * ENC * ENC) : (cWe + (b - 3) * ENC * ENC);
#pragma unroll
    for (int j = 0; j < 4; j++) {
        float acc = 0.f;
        for (int m = 0; m < ENC; m++) acc = fmaf(W_edge[j * ENC + m], We[m * ENC + k], acc);
        g_Weff[b * 4 * ENC + j * ENC + k] = acc;
    }
    float bb = 0.f;
    for (int m = 0; m < ENC; m++) bb = fmaf(b_edge[m], We[m * ENC + k], bb);
    g_beff[b * ENC + k] = bb;
}

// ---------------- node encoder: h0 = x @ W_node + b_node ----------------
__global__ void k_node_enc(const float* __restrict__ x, const float* __restrict__ Wn,
                           const float* __restrict__ bn) {
    __shared__ float sW[8 * ENC];
    __shared__ float sb[ENC];
    int tid = threadIdx.x;
    for (int i = tid; i < 8 * ENC; i += blockDim.x) sW[i] = Wn[i];
    for (int i = tid; i < ENC; i += blockDim.x) sb[i] = bn[i];
    __syncthreads();
    int n = blockIdx.x * blockDim.x + tid;
    if (n >= NN) return;
    float xv[8];
#pragma unroll
    for (int j = 0; j < 8; j++) xv[j] = x[n * 8 + j];
    for (int k = 0; k < ENC; k++) {
        float acc = sb[k];
#pragma unroll
        for (int j = 0; j < 8; j++) acc = fmaf(xv[j], sW[j * ENC + k], acc);
        g_h0[n * ENC + k] = acc;
    }
}

// ---------------- fused xl/xr GEMM: xl = h@Wl, xr = h@Wr (f32x2 packed FMA) ----------------
// block = 256 threads (tx 0..15 -> dim pairs, ty 0..15 -> 4 nodes each), 64-node tile
__global__ __launch_bounds__(256) void k_gemm(int in_sel,
                                              const float* __restrict__ Wl,
                                              const float* __restrict__ Wr) {
    __shared__ float sWl[ENC * ENC];
    __shared__ float sWr[ENC * ENC];
    __shared__ float sH[64 * ENC];
    const float* h = (in_sel == 0) ? g_h0 : ((in_sel == 1) ? g_hA : g_hB);
    int tid = threadIdx.x;
    int tx = tid & 15, ty = tid >> 4;
    int n0 = blockIdx.x * 64;
    for (int i = tid; i < ENC * ENC; i += 256) { sWl[i] = Wl[i]; sWr[i] = Wr[i]; }
    for (int i = tid; i < 64 * ENC; i += 256) {
        int n = n0 + (i >> 6);
        sH[i] = (n < NN) ? h[n0 * ENC + i] : 0.f;
    }
    __syncthreads();

    unsigned long long al0[4], al1[4], ar0[4], ar1[4];
#pragma unroll
    for (int i = 0; i < 4; i++) { al0[i] = 0ull; al1[i] = 0ull; ar0[i] = 0ull; ar1[i] = 0ull; }

#pragma unroll 4
    for (int j = 0; j < ENC; j++) {
        unsigned long long wl0 = *(const unsigned long long*)&sWl[j * ENC + 2 * tx];
        unsigned long long wl1 = *(const unsigned long long*)&sWl[j * ENC + 32 + 2 * tx];
        unsigned long long wr0 = *(const unsigned long long*)&sWr[j * ENC + 2 * tx];
        unsigned long long wr1 = *(const unsigned long long*)&sWr[j * ENC + 32 + 2 * tx];
#pragma unroll
        for (int i = 0; i < 4; i++) {
            unsigned long long hp = pack2(sH[(ty + 16 * i) * ENC + j]);
            fma2(al0[i], wl0, hp);
            fma2(al1[i], wl1, hp);
            fma2(ar0[i], wr0, hp);
            fma2(ar1[i], wr1, hp);
        }
    }
#pragma unroll
    for (int i = 0; i < 4; i++) {
        int n = n0 + ty + 16 * i;
        if (n < NN) {
            *(unsigned long long*)&g_xl[n * ENC + 2 * tx]      = al0[i];
            *(unsigned long long*)&g_xl[n * ENC + 32 + 2 * tx] = al1[i];
            *(unsigned long long*)&g_xr[n * ENC + 2 * tx]      = ar0[i];
            *(unsigned long long*)&g_xr[n * ENC + 32 + 2 * tx] = ar1[i];
        }
    }
}

// ---------------- edge scoring: s[e] = leaky_relu(xl[src]+xr[dst]+ep) . att ----------------
// 8 lanes per edge; Weff/att/beff slices preloaded to registers
__global__ __launch_bounds__(256) void k_score(const float* __restrict__ ea,
                                               const int* __restrict__ src,
                                               const int* __restrict__ dst,
                                               int widx, const float* __restrict__ att) {
    int gt = blockIdx.x * blockDim.x + threadIdx.x;
    int ln8 = gt & 7;
    int grp = gt >> 3;
    int ngroups = (gridDim.x * blockDim.x) >> 3;
    int d0 = ln8 * 8;

    float w0[8], w1[8], w2[8], w3[8], a8[8], be8[8];
    const float* Weff = &g_Weff[widx * 4 * ENC];
    const float* beff = &g_beff[widx * ENC];
#pragma unroll
    for (int t = 0; t < 8; t++) {
        w0[t] = Weff[0 * ENC + d0 + t];
        w1[t] = Weff[1 * ENC + d0 + t];
        w2[t] = Weff[2 * ENC + d0 + t];
        w3[t] = Weff[3 * ENC + d0 + t];
        a8[t] = att[d0 + t];
        be8[t] = beff[d0 + t];
    }

    for (int e = grp; e < NE; e += ngroups) {
        int si = __ldg(&src[e]);
        int di = __ldg(&dst[e]);
        float4 xa = *(const float4*)&g_xl[si * ENC + d0];
        float4 xb = *(const float4*)&g_xl[si * ENC + d0 + 4];
        float4 ra = *(const float4*)&g_xr[di * ENC + d0];
        float4 rb = *(const float4*)&g_xr[di * ENC + d0 + 4];
        float4 ev = *(const float4*)&ea[e * 4];
        float xlv[8] = {xa.x, xa.y, xa.z, xa.w, xb.x, xb.y, xb.z, xb.w};
        float xrv[8] = {ra.x, ra.y, ra.z, ra.w, rb.x, rb.y, rb.z, rb.w};
        float part = 0.f;
#pragma unroll
        for (int t = 0; t < 8; t++) {
            float ep = be8[t];
            ep = fmaf(ev.x, w0[t], ep);
            ep = fmaf(ev.y, w1[t], ep);
            ep = fmaf(ev.z, w2[t], ep);
            ep = fmaf(ev.w, w3[t], ep);
            float m = xlv[t] + xrv[t] + ep;
            float lr = fmaxf(m, 0.f) + 0.2f * fminf(m, 0.f);
            part = fmaf(lr, a8[t], part);
        }
        part += __shfl_xor_sync(0xffffffffu, part, 4);
        part += __shfl_xor_sync(0xffffffffu, part, 2);
        part += __shfl_xor_sync(0xffffffffu, part, 1);
        if (ln8 == 0) g_s[e] = part;
    }
}

// ---------------- per-dst softmax + aggregation (warp per node, atomic-free) ----------------
// out[n] = (sum_e ex_e * xl[src_e]) / (sum_e ex_e) + bias ; optional relu
__global__ __launch_bounds__(256) void k_agg(const int* __restrict__ src,
                                             const float* __restrict__ bias,
                                             int out_sel, int do_relu) {
    int gw = (blockIdx.x * blockDim.x + threadIdx.x) >> 5;
    int lane = threadIdx.x & 31;
    if (gw >= NN) return;
    int node = gw;
    float* hout = (out_sel == 1) ? g_hA : g_hB;

    int beg = g_rowptr[node];
    int end = g_rowptr[node + 1];
    int deg = end - beg;

    float b0 = bias[2 * lane], b1 = bias[2 * lane + 1];
    float o0, o1;

    if (deg == 0) {
        o0 = b0; o1 = b1;
    } else {
        // pass A: segment max
        float mx = -3.0e38f;
        for (int j = lane; j < deg; j += 32) {
            int e = g_eids[beg + j];
            mx = fmaxf(mx, g_s[e]);
        }
#pragma unroll
        for (int d = 16; d; d >>= 1) mx = fmaxf(mx, __shfl_xor_sync(0xffffffffu, mx, d));

        // pass B: unnormalized weighted sum + denom, 32-edge chunks
        float denom = 0.f, acc0 = 0.f, acc1 = 0.f;
        for (int base = 0; base < deg; base += 32) {
            int j = base + lane;
            float ex = 0.f;
            int sj = 0;
            if (j < deg) {
                int e = g_eids[beg + j];
                ex = __expf(g_s[e] - mx);
                sj = __ldg(&src[e]);
            }
            denom += ex;
            int cnt = min(32, deg - base);
            for (int t = 0; t < cnt; t++) {
                float coef = __shfl_sync(0xffffffffu, ex, t);
                int srow = __shfl_sync(0xffffffffu, sj, t);
                float2 v = *(const float2*)&g_xl[srow * ENC + 2 * lane];
                acc0 = fmaf(coef, v.x, acc0);
                acc1 = fmaf(coef, v.y, acc1);
            }
        }
#pragma unroll
        for (int d = 16; d; d >>= 1) denom += __shfl_xor_sync(0xffffffffu, denom, d);
        float inv = 1.f / denom;
        o0 = fmaf(acc0, inv, b0);
        o1 = fmaf(acc1, inv, b1);
    }
    if (do_relu) { o0 = fmaxf(o0, 0.f); o1 = fmaxf(o1, 0.f); }
    float2 ov;
    ov.x = o0; ov.y = o1;
    *(float2*)&hout[node * ENC + 2 * lane] = ov;
}

// ---------------- decoders ----------------
__global__ void k_decode_act(const float* __restrict__ W, const float* __restrict__ b,
                             float* __restrict__ out) {
    __shared__ float sW[ENC * OUTD];
    __shared__ float sb[OUTD];
    int tid = threadIdx.x;
    for (int i = tid; i < ENC * OUTD; i += blockDim.x) sW[i] = W[i];
    if (tid < OUTD) sb[tid] = b[tid];
    __syncthreads();
    int n = blockIdx.x * blockDim.x + tid;
    if (n >= NN) return;
    float acc[OUTD];
#pragma unroll
    for (int c = 0; c < OUTD; c++) acc[c] = sb[c];
    const float* hr = &g_hA[n * ENC];
    for (int k = 0; k < ENC; k++) {
        float hv = hr[k];
#pragma unroll
        for (int c = 0; c < OUTD; c++) acc[c] = fmaf(hv, sW[k * OUTD + c], acc[c]);
    }
#pragma unroll
    for (int c = 0; c < OUTD; c++) out[n * 6 + c] = tanhf(acc[c]);
}

__global__ void k_decode_val(const float* __restrict__ W, const float* __restrict__ b,
                             float* __restrict__ out) {
    __shared__ float sW[ENC];
    __shared__ float sb0;
    int tid = threadIdx.x;
    for (int i = tid; i < ENC; i += blockDim.x) sW[i] = W[i];
    if (tid == 0) sb0 = b[0];
    __syncthreads();
    int n = blockIdx.x * blockDim.x + tid;
    if (n >= NN) return;
    float acc = sb0;
    const float* hr = &g_hB[0];  // placeholder silenced below
    (void)hr;
    const float* h = &g_hA[n * ENC];
    for (int k = 0; k < ENC; k++) acc = fmaf(h[k], sW[k], acc);
    out[n * 6 + 5] = acc;
}

// ---------------- launcher ----------------
extern "C" void kernel_launch(void* const* d_in, const int* in_sizes, int n_in,
                              void* d_out, int out_size) {
    const float* x      = (const float*)d_in[0];
    const float* ea     = (const float*)d_in[1];
    const float* W_node = (const float*)d_in[2];
    const float* b_node = (const float*)d_in[3];
    const float* W_edge = (const float*)d_in[4];
    const float* b_edge = (const float*)d_in[5];
    const float* aWl    = (const float*)d_in[6];
    const float* aWr    = (const float*)d_in[7];
    const float* aWe    = (const float*)d_in[8];
    const float* aatt   = (const float*)d_in[9];
    const float* ab     = (const float*)d_in[10];
    const float* cWl    = (const float*)d_in[11];
    const float* cWr    = (const float*)d_in[12];
    const float* cWe    = (const float*)d_in[13];
    const float* catt   = (const float*)d_in[14];
    const float* cb     = (const float*)d_in[15];
    const float* W_act  = (const float*)d_in[16];
    const float* b_act  = (const float*)d_in[17];
    const float* W_val  = (const float*)d_in[18];
    const float* b_val  = (const float*)d_in[19];
    const int*   src    = (const int*)d_in[20];
    const int*   dst    = (const int*)d_in[21];
    float* out = (float*)d_out;

    // CSR build (per call; atomics + single-block scan)
    k_zero_counts<<<(NN + 255) / 256, 256>>>();
    k_count<<<(NE + 255) / 256, 256>>>(dst);
    k_scan<<<1, 1024>>>();
    k_scatter<<<(NE + 255) / 256, 256>>>(dst);

    // folded edge weights + node encoder
    k_weff<<<6, ENC>>>(W_edge, b_edge, aWe, cWe);
    k_node_enc<<<(NN + 255) / 256, 256>>>(x, W_node, b_node);

    int gemm_blocks  = (NN + 63) / 64;
    int score_blocks = 1184;                     // 148 SMs * 8 blocks, grid-stride
    int agg_blocks   = (NN * 32 + 255) / 256;    // warp per node

    for (int s = 0; s < 2; s++) {
        const float* Wl  = s ? cWl : aWl;
        const float* Wr  = s ? cWr : aWr;
        const float* att = s ? catt : aatt;
        const float* bb  = s ? cb : ab;
        for (int r = 0; r < 3; r++) {
            int in_sel  = (r == 0) ? 0 : ((r == 1) ? 1 : 2);  // h0 -> hA -> hB
            int out_sel = (r == 1) ? 2 : 1;                   // hA, hB, hA
            k_gemm<<<gemm_blocks, 256>>>(in_sel, Wl + r * ENC * ENC, Wr + r * ENC * ENC);
            k_score<<<score_blocks, 256>>>(ea, src, dst, s * 3 + r, att + r * ENC);
            k_agg<<<agg_blocks, 256>>>(src, bb + r * ENC, out_sel, (r < 2) ? 1 : 0);
        }
        if (s == 0)
            k_decode_act<<<(NN + 255) / 256, 256>>>(W_act, b_act, out);
        else
            k_decode_val<<<(NN + 255) / 256, 256>>>(W_val, b_val, out);
    }
}

// round 9
// speedup vs baseline: 1.0000x; 1.0000x over previous
#include <cuda_runtime.h>

#define NN 50000
#define NE 800000
#define ENC 64
#define OUTD 5

// ---------------- scratch (static __device__ — no allocations allowed) ----------------
__device__ float g_h0[NN * ENC];
__device__ float g_hA[NN * ENC];
__device__ float g_hB[NN * ENC];
__device__ float g_xl[NN * ENC];
__device__ float g_xr[NN * ENC];
__device__ float g_s[NE];
__device__ int   g_counts[NN];
__device__ int   g_rowptr[NN + 1];
__device__ int   g_offs[NN];
__device__ int   g_eids[NE];
__device__ float g_Weff[6 * 4 * ENC];   // per (stack,round): W_edge @ We  [4,64]
__device__ float g_beff[6 * ENC];       // per (stack,round): b_edge @ We  [64]

// ---------------- packed f32x2 helpers (sm_103a FFMA2) ----------------
__device__ __forceinline__ unsigned long long pack2(float h) {
    unsigned long long r;
    asm("mov.b64 %0, {%1, %1};" : "=l"(r) : "f"(h));
    return r;
}
__device__ __forceinline__ void fma2(unsigned long long& acc, unsigned long long w,
                                     unsigned long long h) {
    asm("fma.rn.f32x2 %0, %1, %2, %0;" : "+l"(acc) : "l"(w), "l"(h));
}

// ---------------- CSR build ----------------
__global__ void k_zero_counts() {
    int i = blockIdx.x * blockDim.x + threadIdx.x;
    if (i < NN) g_counts[i] = 0;
}

__global__ void k_count(const int* __restrict__ dst) {
    int e = blockIdx.x * blockDim.x + threadIdx.x;
    if (e < NE) atomicAdd(&g_counts[dst[e]], 1);
}

// single block, 1024 threads: exclusive scan of counts -> rowptr (+ copy to offs)
__global__ void k_scan() {
    __shared__ int swarp[32];
    int tid = threadIdx.x, lane = tid & 31, wid = tid >> 5;
    int base = 0;
    for (int start = 0; start < NN; start += 1024) {
        int i = start + tid;
        int c = (i < NN) ? g_counts[i] : 0;
        int v = c;
#pragma unroll
        for (int d = 1; d < 32; d <<= 1) {
            int t = __shfl_up_sync(0xffffffffu, v, d);
            if (lane >= d) v += t;
        }
        if (lane == 31) swarp[wid] = v;
        __syncthreads();
        if (wid == 0) {
            int wv = swarp[lane];
#pragma unroll
            for (int d = 1; d < 32; d <<= 1) {
                int t = __shfl_up_sync(0xffffffffu, wv, d);
                if (lane >= d) wv += t;
            }
            swarp[lane] = wv;
        }
        __syncthreads();
        int prefix = (wid == 0) ? 0 : swarp[wid - 1];
        int excl = base + prefix + v - c;
        if (i < NN) { g_rowptr[i] = excl; g_offs[i] = excl; }
        int tot = swarp[31];
        __syncthreads();   // protect swarp before next iteration overwrites
        base += tot;
    }
    if (tid == 0) g_rowptr[NN] = base;
}

__global__ void k_scatter(const int* __restrict__ dst) {
    int e = blockIdx.x * blockDim.x + threadIdx.x;
    if (e < NE) {
        int p = atomicAdd(&g_offs[dst[e]], 1);
        g_eids[p] = e;
    }
}

// ---------------- edge-weight folding: Weff = W_edge @ We, beff = b_edge @ We ----------------
__global__ void k_weff(const float* __restrict__ W_edge, const float* __restrict__ b_edge,
                       const float* __restrict__ aWe, const float* __restrict__ cWe) {
    int b = blockIdx.x;          // 0..5 : stack*3 + round
    int k = threadIdx.x;         // 0..63
    const float* We = (b < 3) ? (aWe + b * ENC * ENC) : (cWe + (b - 3) * ENC * ENC);
#pragma unroll
    for (int j = 0; j < 4; j++) {
        float acc = 0.f;
        for (int m = 0; m < ENC; m++) acc = fmaf(W_edge[j * ENC + m], We[m * ENC + k], acc);
        g_Weff[b * 4 * ENC + j * ENC + k] = acc;
    }
    float bb = 0.f;
    for (int m = 0; m < ENC; m++) bb = fmaf(b_edge[m], We[m * ENC + k], bb);
    g_beff[b * ENC + k] = bb;
}

// ---------------- node encoder: h0 = x @ W_node + b_node ----------------
__global__ void k_node_enc(const float* __restrict__ x, const float* __restrict__ Wn,
                           const float* __restrict__ bn) {
    __shared__ float sW[8 * ENC];
    __shared__ float sb[ENC];
    int tid = threadIdx.x;
    for (int i = tid; i < 8 * ENC; i += blockDim.x) sW[i] = Wn[i];
    for (int i = tid; i < ENC; i += blockDim.x) sb[i] = bn[i];
    __syncthreads();
    int n = blockIdx.x * blockDim.x + tid;
    if (n >= NN) return;
    float xv[8];
#pragma unroll
    for (int j = 0; j < 8; j++) xv[j] = x[n * 8 + j];
    for (int k = 0; k < ENC; k++) {
        float acc = sb[k];
#pragma unroll
        for (int j = 0; j < 8; j++) acc = fmaf(xv[j], sW[j * ENC + k], acc);
        g_h0[n * ENC + k] = acc;
    }
}

// ---------------- fused xl/xr GEMM: xl = h@Wl, xr = h@Wr (f32x2 packed FMA) ----------------
// block = 256 threads (tx 0..15 -> dim pairs, ty 0..15 -> 4 nodes each), 64-node tile
__global__ __launch_bounds__(256) void k_gemm(int in_sel,
                                              const float* __restrict__ Wl,
                                              const float* __restrict__ Wr) {
    __shared__ float sWl[ENC * ENC];
    __shared__ float sWr[ENC * ENC];
    __shared__ float sH[64 * ENC];
    const float* h = (in_sel == 0) ? g_h0 : ((in_sel == 1) ? g_hA : g_hB);
    int tid = threadIdx.x;
    int tx = tid & 15, ty = tid >> 4;
    int n0 = blockIdx.x * 64;
    for (int i = tid; i < ENC * ENC; i += 256) { sWl[i] = Wl[i]; sWr[i] = Wr[i]; }
    for (int i = tid; i < 64 * ENC; i += 256) {
        int n = n0 + (i >> 6);
        sH[i] = (n < NN) ? h[n0 * ENC + i] : 0.f;
    }
    __syncthreads();

    unsigned long long al0[4], al1[4], ar0[4], ar1[4];
#pragma unroll
    for (int i = 0; i < 4; i++) { al0[i] = 0ull; al1[i] = 0ull; ar0[i] = 0ull; ar1[i] = 0ull; }

#pragma unroll 4
    for (int j = 0; j < ENC; j++) {
        unsigned long long wl0 = *(const unsigned long long*)&sWl[j * ENC + 2 * tx];
        unsigned long long wl1 = *(const unsigned long long*)&sWl[j * ENC + 32 + 2 * tx];
        unsigned long long wr0 = *(const unsigned long long*)&sWr[j * ENC + 2 * tx];
        unsigned long long wr1 = *(const unsigned long long*)&sWr[j * ENC + 32 + 2 * tx];
#pragma unroll
        for (int i = 0; i < 4; i++) {
            unsigned long long hp = pack2(sH[(ty + 16 * i) * ENC + j]);
            fma2(al0[i], wl0, hp);
            fma2(al1[i], wl1, hp);
            fma2(ar0[i], wr0, hp);
            fma2(ar1[i], wr1, hp);
        }
    }
#pragma unroll
    for (int i = 0; i < 4; i++) {
        int n = n0 + ty + 16 * i;
        if (n < NN) {
            *(unsigned long long*)&g_xl[n * ENC + 2 * tx]      = al0[i];
            *(unsigned long long*)&g_xl[n * ENC + 32 + 2 * tx] = al1[i];
            *(unsigned long long*)&g_xr[n * ENC + 2 * tx]      = ar0[i];
            *(unsigned long long*)&g_xr[n * ENC + 32 + 2 * tx] = ar1[i];
        }
    }
}

// ---------------- edge scoring: s[e] = leaky_relu(xl[src]+xr[dst]+ep) . att ----------------
// 8 lanes per edge; Weff/att/beff slices preloaded to registers
__global__ __launch_bounds__(256) void k_score(const float* __restrict__ ea,
                                               const int* __restrict__ src,
                                               const int* __restrict__ dst,
                                               int widx, const float* __restrict__ att) {
    int gt = blockIdx.x * blockDim.x + threadIdx.x;
    int ln8 = gt & 7;
    int grp = gt >> 3;
    int ngroups = (gridDim.x * blockDim.x) >> 3;
    int d0 = ln8 * 8;

    float w0[8], w1[8], w2[8], w3[8], a8[8], be8[8];
    const float* Weff = &g_Weff[widx * 4 * ENC];
    const float* beff = &g_beff[widx * ENC];
#pragma unroll
    for (int t = 0; t < 8; t++) {
        w0[t] = Weff[0 * ENC + d0 + t];
        w1[t] = Weff[1 * ENC + d0 + t];
        w2[t] = Weff[2 * ENC + d0 + t];
        w3[t] = Weff[3 * ENC + d0 + t];
        a8[t] = att[d0 + t];
        be8[t] = beff[d0 + t];
    }

    for (int e = grp; e < NE; e += ngroups) {
        int si = __ldg(&src[e]);
        int di = __ldg(&dst[e]);
        float4 xa = *(const float4*)&g_xl[si * ENC + d0];
        float4 xb = *(const float4*)&g_xl[si * ENC + d0 + 4];
        float4 ra = *(const float4*)&g_xr[di * ENC + d0];
        float4 rb = *(const float4*)&g_xr[di * ENC + d0 + 4];
        float4 ev = *(const float4*)&ea[e * 4];
        float xlv[8] = {xa.x, xa.y, xa.z, xa.w, xb.x, xb.y, xb.z, xb.w};
        float xrv[8] = {ra.x, ra.y, ra.z, ra.w, rb.x, rb.y, rb.z, rb.w};
        float part = 0.f;
#pragma unroll
        for (int t = 0; t < 8; t++) {
            float ep = be8[t];
            ep = fmaf(ev.x, w0[t], ep);
            ep = fmaf(ev.y, w1[t], ep);
            ep = fmaf(ev.z, w2[t], ep);
            ep = fmaf(ev.w, w3[t], ep);
            float m = xlv[t] + xrv[t] + ep;
            float lr = fmaxf(m, 0.f) + 0.2f * fminf(m, 0.f);
            part = fmaf(lr, a8[t], part);
        }
        part += __shfl_xor_sync(0xffffffffu, part, 4);
        part += __shfl_xor_sync(0xffffffffu, part, 2);
        part += __shfl_xor_sync(0xffffffffu, part, 1);
        if (ln8 == 0) g_s[e] = part;
    }
}

// ---------------- per-dst softmax + aggregation (warp per node, atomic-free) ----------------
// out[n] = (sum_e ex_e * xl[src_e]) / (sum_e ex_e) + bias ; optional relu
__global__ __launch_bounds__(256) void k_agg(const int* __restrict__ src,
                                             const float* __restrict__ bias,
                                             int out_sel, int do_relu) {
    int gw = (blockIdx.x * blockDim.x + threadIdx.x) >> 5;
    int lane = threadIdx.x & 31;
    if (gw >= NN) return;
    int node = gw;
    float* hout = (out_sel == 1) ? g_hA : g_hB;

    int beg = g_rowptr[node];
    int end = g_rowptr[node + 1];
    int deg = end - beg;

    float b0 = bias[2 * lane], b1 = bias[2 * lane + 1];
    float o0, o1;

    if (deg == 0) {
        o0 = b0; o1 = b1;
    } else {
        // pass A: segment max
        float mx = -3.0e38f;
        for (int j = lane; j < deg; j += 32) {
            int e = g_eids[beg + j];
            mx = fmaxf(mx, g_s[e]);
        }
#pragma unroll
        for (int d = 16; d; d >>= 1) mx = fmaxf(mx, __shfl_xor_sync(0xffffffffu, mx, d));

        // pass B: unnormalized weighted sum + denom, 32-edge chunks
        float denom = 0.f, acc0 = 0.f, acc1 = 0.f;
        for (int base = 0; base < deg; base += 32) {
            int j = base + lane;
            float ex = 0.f;
            int sj = 0;
            if (j < deg) {
                int e = g_eids[beg + j];
                ex = __expf(g_s[e] - mx);
                sj = __ldg(&src[e]);
            }
            denom += ex;
            int cnt = min(32, deg - base);
            for (int t = 0; t < cnt; t++) {
                float coef = __shfl_sync(0xffffffffu, ex, t);
                int srow = __shfl_sync(0xffffffffu, sj, t);
                float2 v = *(const float2*)&g_xl[srow * ENC + 2 * lane];
                acc0 = fmaf(coef, v.x, acc0);
                acc1 = fmaf(coef, v.y, acc1);
            }
        }
#pragma unroll
        for (int d = 16; d; d >>= 1) denom += __shfl_xor_sync(0xffffffffu, denom, d);
        float inv = 1.f / denom;
        o0 = fmaf(acc0, inv, b0);
        o1 = fmaf(acc1, inv, b1);
    }
    if (do_relu) { o0 = fmaxf(o0, 0.f); o1 = fmaxf(o1, 0.f); }
    float2 ov;
    ov.x = o0; ov.y = o1;
    *(float2*)&hout[node * ENC + 2 * lane] = ov;
}

// ---------------- decoders ----------------
__global__ void k_decode_act(const float* __restrict__ W, const float* __restrict__ b,
                             float* __restrict__ out) {
    __shared__ float sW[ENC * OUTD];
    __shared__ float sb[OUTD];
    int tid = threadIdx.x;
    for (int i = tid; i < ENC * OUTD; i += blockDim.x) sW[i] = W[i];
    if (tid < OUTD) sb[tid] = b[tid];
    __syncthreads();
    int n = blockIdx.x * blockDim.x + tid;
    if (n >= NN) return;
    float acc[OUTD];
#pragma unroll
    for (int c = 0; c < OUTD; c++) acc[c] = sb[c];
    const float* hr = &g_hA[n * ENC];
    for (int k = 0; k < ENC; k++) {
        float hv = hr[k];
#pragma unroll
        for (int c = 0; c < OUTD; c++) acc[c] = fmaf(hv, sW[k * OUTD + c], acc[c]);
    }
#pragma unroll
    for (int c = 0; c < OUTD; c++) out[n * 6 + c] = tanhf(acc[c]);
}

__global__ void k_decode_val(const float* __restrict__ W, const float* __restrict__ b,
                             float* __restrict__ out) {
    __shared__ float sW[ENC];
    __shared__ float sb0;
    int tid = threadIdx.x;
    for (int i = tid; i < ENC; i += blockDim.x) sW[i] = W[i];
    if (tid == 0) sb0 = b[0];
    __syncthreads();
    int n = blockIdx.x * blockDim.x + tid;
    if (n >= NN) return;
    float acc = sb0;
    const float* hr = &g_hB[0];  // placeholder silenced below
    (void)hr;
    const float* h = &g_hA[n * ENC];
    for (int k = 0; k < ENC; k++) acc = fmaf(h[k], sW[k], acc);
    out[n * 6 + 5] = acc;
}

// ---------------- launcher ----------------
extern "C" void kernel_launch(void* const* d_in, const int* in_sizes, int n_in,
                              void* d_out, int out_size) {
    const float* x      = (const float*)d_in[0];
    const float* ea     = (const float*)d_in[1];
    const float* W_node = (const float*)d_in[2];
    const float* b_node = (const float*)d_in[3];
    const float* W_edge = (const float*)d_in[4];
    const float* b_edge = (const float*)d_in[5];
    const float* aWl    = (const float*)d_in[6];
    const float* aWr    = (const float*)d_in[7];
    const float* aWe    = (const float*)d_in[8];
    const float* aatt   = (const float*)d_in[9];
    const float* ab     = (const float*)d_in[10];
    const float* cWl    = (const float*)d_in[11];
    const float* cWr    = (const float*)d_in[12];
    const float* cWe    = (const float*)d_in[13];
    const float* catt   = (const float*)d_in[14];
    const float* cb     = (const float*)d_in[15];
    const float* W_act  = (const float*)d_in[16];
    const float* b_act  = (const float*)d_in[17];
    const float* W_val  = (const float*)d_in[18];
    const float* b_val  = (const float*)d_in[19];
    const int*   src    = (const int*)d_in[20];
    const int*   dst    = (const int*)d_in[21];
    float* out = (float*)d_out;

    // CSR build (per call; atomics + single-block scan)
    k_zero_counts<<<(NN + 255) / 256, 256>>>();
    k_count<<<(NE + 255) / 256, 256>>>(dst);
    k_scan<<<1, 1024>>>();
    k_scatter<<<(NE + 255) / 256, 256>>>(dst);

    // folded edge weights + node encoder
    k_weff<<<6, ENC>>>(W_edge, b_edge, aWe, cWe);
    k_node_enc<<<(NN + 255) / 256, 256>>>(x, W_node, b_node);

    int gemm_blocks  = (NN + 63) / 64;
    int score_blocks = 1184;                     // 148 SMs * 8 blocks, grid-stride
    int agg_blocks   = (NN * 32 + 255) / 256;    // warp per node

    for (int s = 0; s < 2; s++) {
        const float* Wl  = s ? cWl : aWl;
        const float* Wr  = s ? cWr : aWr;
        const float* att = s ? catt : aatt;
        const float* bb  = s ? cb : ab;
        for (int r = 0; r < 3; r++) {
            int in_sel  = (r == 0) ? 0 : ((r == 1) ? 1 : 2);  // h0 -> hA -> hB
            int out_sel = (r == 1) ? 2 : 1;                   // hA, hB, hA
            k_gemm<<<gemm_blocks, 256>>>(in_sel, Wl + r * ENC * ENC, Wr + r * ENC * ENC);
            k_score<<<score_blocks, 256>>>(ea, src, dst, s * 3 + r, att + r * ENC);
            k_agg<<<agg_blocks, 256>>>(src, bb + r * ENC, out_sel, (r < 2) ? 1 : 0);
        }
        if (s == 0)
            k_decode_act<<<(NN + 255) / 256, 256>>>(W_act, b_act, out);
        else
            k_decode_val<<<(NN + 255) / 256, 256>>>(W_val, b_val, out);
    }
}

// round 10
// speedup vs baseline: 1.0754x; 1.0754x over previous
#include <cuda_runtime.h>

#define NN 50000
#define NE 800000
#define ENC 64
#define OUTD 5

// ---------------- scratch (static __device__ — no allocations allowed) ----------------
__device__ float g_h0[NN * ENC];
__device__ float g_hA[NN * ENC];   // actor ping
__device__ float g_hB[NN * ENC];   // actor pong
__device__ float g_hC[NN * ENC];   // critic ping
__device__ float g_hD[NN * ENC];   // critic pong
__device__ float g_xlA[NN * ENC];
__device__ float g_xrA[NN * ENC];
__device__ float g_xlC[NN * ENC];
__device__ float g_xrC[NN * ENC];
__device__ int    g_counts[NN];
__device__ int    g_rowptr[NN + 1];
__device__ int    g_offs[NN];
__device__ int    g_psrc[NE];      // src permuted to CSR(dst) order
__device__ float4 g_pea[NE];       // edge_attr permuted to CSR(dst) order
__device__ float  g_Weff[6 * 4 * ENC];   // per (stack,round): W_edge @ We  [4,64]
__device__ float  g_beff[6 * ENC];       // per (stack,round): b_edge @ We  [64]

// ---------------- packed f32x2 helpers (sm_103a FFMA2) ----------------
__device__ __forceinline__ unsigned long long pack2(float h) {
    unsigned long long r;
    asm("mov.b64 %0, {%1, %1};" : "=l"(r) : "f"(h));
    return r;
}
__device__ __forceinline__ void fma2(unsigned long long& acc, unsigned long long w,
                                     unsigned long long h) {
    asm("fma.rn.f32x2 %0, %1, %2, %0;" : "+l"(acc) : "l"(w), "l"(h));
}

// ---------------- CSR build ----------------
__global__ void k_zero_counts() {
    int i = blockIdx.x * blockDim.x + threadIdx.x;
    if (i < NN) g_counts[i] = 0;
}

__global__ void k_count(const int* __restrict__ dst) {
    int e = blockIdx.x * blockDim.x + threadIdx.x;
    if (e < NE) atomicAdd(&g_counts[dst[e]], 1);
}

// single block, 1024 threads: exclusive scan of counts -> rowptr (+ copy to offs)
__global__ void k_scan() {
    __shared__ int swarp[32];
    int tid = threadIdx.x, lane = tid & 31, wid = tid >> 5;
    int base = 0;
    for (int start = 0; start < NN; start += 1024) {
        int i = start + tid;
        int c = (i < NN) ? g_counts[i] : 0;
        int v = c;
#pragma unroll
        for (int d = 1; d < 32; d <<= 1) {
            int t = __shfl_up_sync(0xffffffffu, v, d);
            if (lane >= d) v += t;
        }
        if (lane == 31) swarp[wid] = v;
        __syncthreads();
        if (wid == 0) {
            int wv = swarp[lane];
#pragma unroll
            for (int d = 1; d < 32; d <<= 1) {
                int t = __shfl_up_sync(0xffffffffu, wv, d);
                if (lane >= d) wv += t;
            }
            swarp[lane] = wv;
        }
        __syncthreads();
        int prefix = (wid == 0) ? 0 : swarp[wid - 1];
        int excl = base + prefix + v - c;
        if (i < NN) { g_rowptr[i] = excl; g_offs[i] = excl; }
        int tot = swarp[31];
        __syncthreads();
        base += tot;
    }
    if (tid == 0) g_rowptr[NN] = base;
}

// scatter edges into CSR order, permuting src and edge_attr along the way
__global__ void k_scatter(const int* __restrict__ dst, const int* __restrict__ src,
                          const float4* __restrict__ ea) {
    int e = blockIdx.x * blockDim.x + threadIdx.x;
    if (e < NE) {
        int p = atomicAdd(&g_offs[dst[e]], 1);
        g_psrc[p] = src[e];
        g_pea[p]  = ea[e];
    }
}

// ---------------- edge-weight folding: Weff = W_edge @ We, beff = b_edge @ We ----------------
__global__ void k_weff(const float* __restrict__ W_edge, const float* __restrict__ b_edge,
                       const float* __restrict__ aWe, const float* __restrict__ cWe) {
    int b = blockIdx.x;          // 0..5 : stack*3 + round
    int k = threadIdx.x;         // 0..63
    const float* We = (b < 3) ? (aWe + b * ENC * ENC) : (cWe + (b - 3) * ENC * ENC);
#pragma unroll
    for (int j = 0; j < 4; j++) {
        float acc = 0.f;
        for (int m = 0; m < ENC; m++) acc = fmaf(W_edge[j * ENC + m], We[m * ENC + k], acc);
        g_Weff[b * 4 * ENC + j * ENC + k] = acc;
    }
    float bb = 0.f;
    for (int m = 0; m < ENC; m++) bb = fmaf(b_edge[m], We[m * ENC + k], bb);
    g_beff[b * ENC + k] = bb;
}

// ---------------- node encoder: h0 = x @ W_node + b_node ----------------
__global__ void k_node_enc(const float* __restrict__ x, const float* __restrict__ Wn,
                           const float* __restrict__ bn) {
    __shared__ float sW[8 * ENC];
    __shared__ float sb[ENC];
    int tid = threadIdx.x;
    for (int i = tid; i < 8 * ENC; i += blockDim.x) sW[i] = Wn[i];
    for (int i = tid; i < ENC; i += blockDim.x) sb[i] = bn[i];
    __syncthreads();
    int n = blockIdx.x * blockDim.x + tid;
    if (n >= NN) return;
    float xv[8];
#pragma unroll
    for (int j = 0; j < 8; j++) xv[j] = x[n * 8 + j];
    for (int k = 0; k < ENC; k++) {
        float acc = sb[k];
#pragma unroll
        for (int j = 0; j < 8; j++) acc = fmaf(xv[j], sW[j * ENC + k], acc);
        g_h0[n * ENC + k] = acc;
    }
}

// ---------------- fused xl/xr GEMM: xl = h@Wl, xr = h@Wr (f32x2 packed FMA) ----------------
// in_sel: 0=h0 1=hA 2=hB 3=hC 4=hD ; stack_sel: 0 -> (xlA,xrA), 1 -> (xlC,xrC)
__global__ __launch_bounds__(256) void k_gemm(int in_sel, int stack_sel,
                                              const float* __restrict__ Wl,
                                              const float* __restrict__ Wr) {
    __shared__ float sWl[ENC * ENC];
    __shared__ float sWr[ENC * ENC];
    __shared__ float sH[64 * ENC];
    const float* h = (in_sel == 0) ? g_h0
                   : (in_sel == 1) ? g_hA
                   : (in_sel == 2) ? g_hB
                   : (in_sel == 3) ? g_hC : g_hD;
    float* oxl = stack_sel ? g_xlC : g_xlA;
    float* oxr = stack_sel ? g_xrC : g_xrA;
    int tid = threadIdx.x;
    int tx = tid & 15, ty = tid >> 4;
    int n0 = blockIdx.x * 64;
    for (int i = tid; i < ENC * ENC; i += 256) { sWl[i] = Wl[i]; sWr[i] = Wr[i]; }
    for (int i = tid; i < 64 * ENC; i += 256) {
        int n = n0 + (i >> 6);
        sH[i] = (n < NN) ? h[n0 * ENC + i] : 0.f;
    }
    __syncthreads();

    unsigned long long al0[4], al1[4], ar0[4], ar1[4];
#pragma unroll
    for (int i = 0; i < 4; i++) { al0[i] = 0ull; al1[i] = 0ull; ar0[i] = 0ull; ar1[i] = 0ull; }

#pragma unroll 4
    for (int j = 0; j < ENC; j++) {
        unsigned long long wl0 = *(const unsigned long long*)&sWl[j * ENC + 2 * tx];
        unsigned long long wl1 = *(const unsigned long long*)&sWl[j * ENC + 32 + 2 * tx];
        unsigned long long wr0 = *(const unsigned long long*)&sWr[j * ENC + 2 * tx];
        unsigned long long wr1 = *(const unsigned long long*)&sWr[j * ENC + 32 + 2 * tx];
#pragma unroll
        for (int i = 0; i < 4; i++) {
            unsigned long long hp = pack2(sH[(ty + 16 * i) * ENC + j]);
            fma2(al0[i], wl0, hp);
            fma2(al1[i], wl1, hp);
            fma2(ar0[i], wr0, hp);
            fma2(ar1[i], wr1, hp);
        }
    }
#pragma unroll
    for (int i = 0; i < 4; i++) {
        int n = n0 + ty + 16 * i;
        if (n < NN) {
            *(unsigned long long*)&oxl[n * ENC + 2 * tx]      = al0[i];
            *(unsigned long long*)&oxl[n * ENC + 32 + 2 * tx] = al1[i];
            *(unsigned long long*)&oxr[n * ENC + 2 * tx]      = ar0[i];
            *(unsigned long long*)&oxr[n * ENC + 32 + 2 * tx] = ar1[i];
        }
    }
}

// ---------------- fused score + online-softmax aggregation, both stacks ----------------
// warp per node; lane owns dims {2*lane, 2*lane+1}
// out[n] = (sum_e exp(s_e - mx) * xl[src_e]) / (sum_e exp(s_e - mx)) + bias
__global__ __launch_bounds__(256) void k_fused(int widx,
                                               const float* __restrict__ aatt,
                                               const float* __restrict__ catt,
                                               const float* __restrict__ ab,
                                               const float* __restrict__ cb,
                                               int out_sel, int do_relu) {
    int gw = (blockIdx.x * blockDim.x + threadIdx.x) >> 5;
    if (gw >= NN) return;
    int lane = threadIdx.x & 31;
    int d0 = 2 * lane;
    float* outA = out_sel ? g_hB : g_hA;
    float* outC = out_sel ? g_hD : g_hC;

    int beg = g_rowptr[gw];
    int deg = g_rowptr[gw + 1] - beg;

    float bA0 = ab[d0], bA1 = ab[d0 + 1];
    float bC0 = cb[d0], bC1 = cb[d0 + 1];
    float oA0, oA1, oC0, oC1;

    if (deg == 0) {
        oA0 = bA0; oA1 = bA1; oC0 = bC0; oC1 = bC1;
    } else {
        const float* WA = &g_Weff[widx * 4 * ENC];
        const float* WC = &g_Weff[(widx + 3) * 4 * ENC];
        float wA[4][2], wC[4][2];
#pragma unroll
        for (int j = 0; j < 4; j++) {
            wA[j][0] = WA[j * ENC + d0]; wA[j][1] = WA[j * ENC + d0 + 1];
            wC[j][0] = WC[j * ENC + d0]; wC[j][1] = WC[j * ENC + d0 + 1];
        }
        float beA0 = g_beff[widx * ENC + d0],        beA1 = g_beff[widx * ENC + d0 + 1];
        float beC0 = g_beff[(widx + 3) * ENC + d0],  beC1 = g_beff[(widx + 3) * ENC + d0 + 1];
        float atA0 = aatt[d0], atA1 = aatt[d0 + 1];
        float atC0 = catt[d0], atC1 = catt[d0 + 1];
        float2 xrA = *(const float2*)&g_xrA[gw * ENC + d0];
        float2 xrC = *(const float2*)&g_xrC[gw * ENC + d0];

        float mA = -3.0e38f, dA = 0.f, aA0 = 0.f, aA1 = 0.f;
        float mC = -3.0e38f, dC = 0.f, aC0 = 0.f, aC1 = 0.f;

#pragma unroll 2
        for (int j = 0; j < deg; j++) {
            int   sidx = __ldg(&g_psrc[beg + j]);          // warp-broadcast
            float4 ev  = __ldg(&g_pea[beg + j]);           // warp-broadcast
            float2 xlA = *(const float2*)&g_xlA[sidx * ENC + d0];
            float2 xlC = *(const float2*)&g_xlC[sidx * ENC + d0];

            // ep = ea @ Weff + beff  (2 dims per lane, per stack)
            float epA0 = beA0, epA1 = beA1, epC0 = beC0, epC1 = beC1;
            epA0 = fmaf(ev.x, wA[0][0], epA0); epA1 = fmaf(ev.x, wA[0][1], epA1);
            epA0 = fmaf(ev.y, wA[1][0], epA0); epA1 = fmaf(ev.y, wA[1][1], epA1);
            epA0 = fmaf(ev.z, wA[2][0], epA0); epA1 = fmaf(ev.z, wA[2][1], epA1);
            epA0 = fmaf(ev.w, wA[3][0], epA0); epA1 = fmaf(ev.w, wA[3][1], epA1);
            epC0 = fmaf(ev.x, wC[0][0], epC0); epC1 = fmaf(ev.x, wC[0][1], epC1);
            epC0 = fmaf(ev.y, wC[1][0], epC0); epC1 = fmaf(ev.y, wC[1][1], epC1);
            epC0 = fmaf(ev.z, wC[2][0], epC0); epC1 = fmaf(ev.z, wC[2][1], epC1);
            epC0 = fmaf(ev.w, wC[3][0], epC0); epC1 = fmaf(ev.w, wC[3][1], epC1);

            float mA0 = xlA.x + xrA.x + epA0;
            float mA1 = xlA.y + xrA.y + epA1;
            float mC0 = xlC.x + xrC.x + epC0;
            float mC1 = xlC.y + xrC.y + epC1;
            float lA0 = fmaxf(mA0, 0.f) + 0.2f * fminf(mA0, 0.f);
            float lA1 = fmaxf(mA1, 0.f) + 0.2f * fminf(mA1, 0.f);
            float lC0 = fmaxf(mC0, 0.f) + 0.2f * fminf(mC0, 0.f);
            float lC1 = fmaxf(mC1, 0.f) + 0.2f * fminf(mC1, 0.f);
            float pA = fmaf(lA0, atA0, lA1 * atA1);
            float pC = fmaf(lC0, atC0, lC1 * atC1);

            // two interleaved butterfly reductions (independent -> ILP)
#pragma unroll
            for (int d = 16; d; d >>= 1) {
                pA += __shfl_xor_sync(0xffffffffu, pA, d);
                pC += __shfl_xor_sync(0xffffffffu, pC, d);
            }

            // online softmax, actor
            float nmA = fmaxf(mA, pA);
            float cA  = __expf(mA - nmA);
            float exA = __expf(pA - nmA);
            dA  = fmaf(dA, cA, exA);
            aA0 = fmaf(aA0, cA, exA * xlA.x);
            aA1 = fmaf(aA1, cA, exA * xlA.y);
            mA  = nmA;
            // online softmax, critic
            float nmC = fmaxf(mC, pC);
            float cC  = __expf(mC - nmC);
            float exC = __expf(pC - nmC);
            dC  = fmaf(dC, cC, exC);
            aC0 = fmaf(aC0, cC, exC * xlC.x);
            aC1 = fmaf(aC1, cC, exC * xlC.y);
            mC  = nmC;
        }
        float invA = 1.f / dA, invC = 1.f / dC;
        oA0 = fmaf(aA0, invA, bA0); oA1 = fmaf(aA1, invA, bA1);
        oC0 = fmaf(aC0, invC, bC0); oC1 = fmaf(aC1, invC, bC1);
    }
    if (do_relu) {
        oA0 = fmaxf(oA0, 0.f); oA1 = fmaxf(oA1, 0.f);
        oC0 = fmaxf(oC0, 0.f); oC1 = fmaxf(oC1, 0.f);
    }
    float2 va; va.x = oA0; va.y = oA1;
    float2 vc; vc.x = oC0; vc.y = oC1;
    *(float2*)&outA[gw * ENC + d0] = va;
    *(float2*)&outC[gw * ENC + d0] = vc;
}

// ---------------- decoders ----------------
__global__ void k_decode_act(const float* __restrict__ W, const float* __restrict__ b,
                             float* __restrict__ out) {
    __shared__ float sW[ENC * OUTD];
    __shared__ float sb[OUTD];
    int tid = threadIdx.x;
    for (int i = tid; i < ENC * OUTD; i += blockDim.x) sW[i] = W[i];
    if (tid < OUTD) sb[tid] = b[tid];
    __syncthreads();
    int n = blockIdx.x * blockDim.x + tid;
    if (n >= NN) return;
    float acc[OUTD];
#pragma unroll
    for (int c = 0; c < OUTD; c++) acc[c] = sb[c];
    const float* hr = &g_hA[n * ENC];   // actor final (round 2 writes hA)
    for (int k = 0; k < ENC; k++) {
        float hv = hr[k];
#pragma unroll
        for (int c = 0; c < OUTD; c++) acc[c] = fmaf(hv, sW[k * OUTD + c], acc[c]);
    }
#pragma unroll
    for (int c = 0; c < OUTD; c++) out[n * 6 + c] = tanhf(acc[c]);
}

__global__ void k_decode_val(const float* __restrict__ W, const float* __restrict__ b,
                             float* __restrict__ out) {
    __shared__ float sW[ENC];
    __shared__ float sb0;
    int tid = threadIdx.x;
    for (int i = tid; i < ENC; i += blockDim.x) sW[i] = W[i];
    if (tid == 0) sb0 = b[0];
    __syncthreads();
    int n = blockIdx.x * blockDim.x + tid;
    if (n >= NN) return;
    float acc = sb0;
    const float* hr = &g_hC[n * ENC];   // critic final (round 2 writes hC)
    for (int k = 0; k < ENC; k++) acc = fmaf(hr[k], sW[k], acc);
    out[n * 6 + 5] = acc;
}

// ---------------- launcher ----------------
extern "C" void kernel_launch(void* const* d_in, const int* in_sizes, int n_in,
                              void* d_out, int out_size) {
    const float* x      = (const float*)d_in[0];
    const float* ea     = (const float*)d_in[1];
    const float* W_node = (const float*)d_in[2];
    const float* b_node = (const float*)d_in[3];
    const float* W_edge = (const float*)d_in[4];
    const float* b_edge = (const float*)d_in[5];
    const float* aWl    = (const float*)d_in[6];
    const float* aWr    = (const float*)d_in[7];
    const float* aWe    = (const float*)d_in[8];
    const float* aatt   = (const float*)d_in[9];
    const float* ab     = (const float*)d_in[10];
    const float* cWl    = (const float*)d_in[11];
    const float* cWr    = (const float*)d_in[12];
    const float* cWe    = (const float*)d_in[13];
    const float* catt   = (const float*)d_in[14];
    const float* cb     = (const float*)d_in[15];
    const float* W_act  = (const float*)d_in[16];
    const float* b_act  = (const float*)d_in[17];
    const float* W_val  = (const float*)d_in[18];
    const float* b_val  = (const float*)d_in[19];
    const int*   src    = (const int*)d_in[20];
    const int*   dst    = (const int*)d_in[21];
    float* out = (float*)d_out;

    // CSR build with src/edge_attr permutation
    k_zero_counts<<<(NN + 255) / 256, 256>>>();
    k_count<<<(NE + 255) / 256, 256>>>(dst);
    k_scan<<<1, 1024>>>();
    k_scatter<<<(NE + 255) / 256, 256>>>(dst, src, (const float4*)ea);

    // folded edge weights + node encoder
    k_weff<<<6, ENC>>>(W_edge, b_edge, aWe, cWe);
    k_node_enc<<<(NN + 255) / 256, 256>>>(x, W_node, b_node);

    int gemm_blocks  = (NN + 63) / 64;
    int fused_blocks = (NN * 32 + 255) / 256;   // warp per node

    // actor chain: h0 -> hA -> hB -> hA ; critic chain: h0 -> hC -> hD -> hC
    // in_sel per round:  actor {0,1,2}, critic {0,3,4} ; out_sel {0,1,0}
    const int inA[3] = {0, 1, 2};
    const int inC[3] = {0, 3, 4};
    const int osel[3] = {0, 1, 0};

    for (int r = 0; r < 3; r++) {
        k_gemm<<<gemm_blocks, 256>>>(inA[r], 0, aWl + r * ENC * ENC, aWr + r * ENC * ENC);
        k_gemm<<<gemm_blocks, 256>>>(inC[r], 1, cWl + r * ENC * ENC, cWr + r * ENC * ENC);
        k_fused<<<fused_blocks, 256>>>(r, aatt + r * ENC, catt + r * ENC,
                                       ab + r * ENC, cb + r * ENC,
                                       osel[r], (r < 2) ? 1 : 0);
    }

    k_decode_act<<<(NN + 255) / 256, 256>>>(W_act, b_act, out);
    k_decode_val<<<(NN + 255) / 256, 256>>>(W_val, b_val, out);
}

// round 12
// speedup vs baseline: 1.1936x; 1.1099x over previous
#include <cuda_runtime.h>

#define NN 50000
#define NE 800000
#define ENC 64
#define OUTD 5

// ---------------- scratch (static __device__ — no allocations allowed) ----------------
__device__ float g_h0[NN * ENC];
__device__ float g_hA[NN * ENC];   // actor ping
__device__ float g_hB[NN * ENC];   // actor pong
__device__ float g_hC[NN * ENC];   // critic ping
__device__ float g_hD[NN * ENC];   // critic pong
__device__ float g_xlA[NN * ENC];
__device__ float g_xrA[NN * ENC];
__device__ float g_xlC[NN * ENC];
__device__ float g_xrC[NN * ENC];
__device__ int    g_counts[NN];
__device__ int    g_rowptr[NN + 1];
__device__ int    g_offs[NN];
__device__ int    g_psrc[NE];      // src permuted to CSR(dst) order
__device__ float4 g_pea[NE];       // edge_attr permuted to CSR(dst) order
__device__ float  g_Weff[6 * 4 * ENC];   // per (stack,round): W_edge @ We  [4,64]
__device__ float  g_beff[6 * ENC];       // per (stack,round): b_edge @ We  [64]

// ---------------- packed f32x2 helpers (sm_103a FFMA2) ----------------
__device__ __forceinline__ unsigned long long pack2(float h) {
    unsigned long long r;
    asm("mov.b64 %0, {%1, %1};" : "=l"(r) : "f"(h));
    return r;
}
__device__ __forceinline__ void fma2(unsigned long long& acc, unsigned long long w,
                                     unsigned long long h) {
    asm("fma.rn.f32x2 %0, %1, %2, %0;" : "+l"(acc) : "l"(w), "l"(h));
}

// ---------------- CSR build ----------------
__global__ void k_zero_counts() {
    int i = blockIdx.x * blockDim.x + threadIdx.x;
    if (i < NN) g_counts[i] = 0;
}

__global__ void k_count(const int* __restrict__ dst) {
    int e = blockIdx.x * blockDim.x + threadIdx.x;
    if (e < NE) atomicAdd(&g_counts[dst[e]], 1);
}

// single block, 1024 threads: exclusive scan of counts -> rowptr (+ copy to offs)
__global__ void k_scan() {
    __shared__ int swarp[32];
    int tid = threadIdx.x, lane = tid & 31, wid = tid >> 5;
    int base = 0;
    for (int start = 0; start < NN; start += 1024) {
        int i = start + tid;
        int c = (i < NN) ? g_counts[i] : 0;
        int v = c;
#pragma unroll
        for (int d = 1; d < 32; d <<= 1) {
            int t = __shfl_up_sync(0xffffffffu, v, d);
            if (lane >= d) v += t;
        }
        if (lane == 31) swarp[wid] = v;
        __syncthreads();
        if (wid == 0) {
            int wv = swarp[lane];
#pragma unroll
            for (int d = 1; d < 32; d <<= 1) {
                int t = __shfl_up_sync(0xffffffffu, wv, d);
                if (lane >= d) wv += t;
            }
            swarp[lane] = wv;
        }
        __syncthreads();
        int prefix = (wid == 0) ? 0 : swarp[wid - 1];
        int excl = base + prefix + v - c;
        if (i < NN) { g_rowptr[i] = excl; g_offs[i] = excl; }
        int tot = swarp[31];
        __syncthreads();
        base += tot;
    }
    if (tid == 0) g_rowptr[NN] = base;
}

// scatter edges into CSR order, permuting src and edge_attr along the way
__global__ void k_scatter(const int* __restrict__ dst, const int* __restrict__ src,
                          const float4* __restrict__ ea) {
    int e = blockIdx.x * blockDim.x + threadIdx.x;
    if (e < NE) {
        int p = atomicAdd(&g_offs[dst[e]], 1);
        g_psrc[p] = src[e];
        g_pea[p]  = ea[e];
    }
}

// ---------------- edge-weight folding: Weff = W_edge @ We, beff = b_edge @ We ----------------
__global__ void k_weff(const float* __restrict__ W_edge, const float* __restrict__ b_edge,
                       const float* __restrict__ aWe, const float* __restrict__ cWe) {
    int b = blockIdx.x;          // 0..5 : stack*3 + round
    int k = threadIdx.x;         // 0..63
    const float* We = (b < 3) ? (aWe + b * ENC * ENC) : (cWe + (b - 3) * ENC * ENC);
#pragma unroll
    for (int j = 0; j < 4; j++) {
        float acc = 0.f;
        for (int m = 0; m < ENC; m++) acc = fmaf(W_edge[j * ENC + m], We[m * ENC + k], acc);
        g_Weff[b * 4 * ENC + j * ENC + k] = acc;
    }
    float bb = 0.f;
    for (int m = 0; m < ENC; m++) bb = fmaf(b_edge[m], We[m * ENC + k], bb);
    g_beff[b * ENC + k] = bb;
}

// ---------------- node encoder: h0 = x @ W_node + b_node ----------------
__global__ void k_node_enc(const float* __restrict__ x, const float* __restrict__ Wn,
                           const float* __restrict__ bn) {
    __shared__ float sW[8 * ENC];
    __shared__ float sb[ENC];
    int tid = threadIdx.x;
    for (int i = tid; i < 8 * ENC; i += blockDim.x) sW[i] = Wn[i];
    for (int i = tid; i < ENC; i += blockDim.x) sb[i] = bn[i];
    __syncthreads();
    int n = blockIdx.x * blockDim.x + tid;
    if (n >= NN) return;
    float xv[8];
#pragma unroll
    for (int j = 0; j < 8; j++) xv[j] = x[n * 8 + j];
    for (int k = 0; k < ENC; k++) {
        float acc = sb[k];
#pragma unroll
        for (int j = 0; j < 8; j++) acc = fmaf(xv[j], sW[j * ENC + k], acc);
        g_h0[n * ENC + k] = acc;
    }
}

// ---------------- fused xl/xr GEMM: xl = h@Wl, xr = h@Wr (f32x2 packed FMA) ----------------
// in_sel: 0=h0 1=hA 2=hB 3=hC 4=hD ; stack_sel: 0 -> (xlA,xrA), 1 -> (xlC,xrC)
__global__ __launch_bounds__(256) void k_gemm(int in_sel, int stack_sel,
                                              const float* __restrict__ Wl,
                                              const float* __restrict__ Wr) {
    __shared__ float sWl[ENC * ENC];
    __shared__ float sWr[ENC * ENC];
    __shared__ float sH[64 * ENC];
    const float* h = (in_sel == 0) ? g_h0
                   : (in_sel == 1) ? g_hA
                   : (in_sel == 2) ? g_hB
                   : (in_sel == 3) ? g_hC : g_hD;
    float* oxl = stack_sel ? g_xlC : g_xlA;
    float* oxr = stack_sel ? g_xrC : g_xrA;
    int tid = threadIdx.x;
    int tx = tid & 15, ty = tid >> 4;
    int n0 = blockIdx.x * 64;
    for (int i = tid; i < ENC * ENC; i += 256) { sWl[i] = Wl[i]; sWr[i] = Wr[i]; }
    for (int i = tid; i < 64 * ENC; i += 256) {
        int n = n0 + (i >> 6);
        sH[i] = (n < NN) ? h[n0 * ENC + i] : 0.f;
    }
    __syncthreads();

    unsigned long long al0[4], al1[4], ar0[4], ar1[4];
#pragma unroll
    for (int i = 0; i < 4; i++) { al0[i] = 0ull; al1[i] = 0ull; ar0[i] = 0ull; ar1[i] = 0ull; }

#pragma unroll 4
    for (int j = 0; j < ENC; j++) {
        unsigned long long wl0 = *(const unsigned long long*)&sWl[j * ENC + 2 * tx];
        unsigned long long wl1 = *(const unsigned long long*)&sWl[j * ENC + 32 + 2 * tx];
        unsigned long long wr0 = *(const unsigned long long*)&sWr[j * ENC + 2 * tx];
        unsigned long long wr1 = *(const unsigned long long*)&sWr[j * ENC + 32 + 2 * tx];
#pragma unroll
        for (int i = 0; i < 4; i++) {
            unsigned long long hp = pack2(sH[(ty + 16 * i) * ENC + j]);
            fma2(al0[i], wl0, hp);
            fma2(al1[i], wl1, hp);
            fma2(ar0[i], wr0, hp);
            fma2(ar1[i], wr1, hp);
        }
    }
#pragma unroll
    for (int i = 0; i < 4; i++) {
        int n = n0 + ty + 16 * i;
        if (n < NN) {
            *(unsigned long long*)&oxl[n * ENC + 2 * tx]      = al0[i];
            *(unsigned long long*)&oxl[n * ENC + 32 + 2 * tx] = al1[i];
            *(unsigned long long*)&oxr[n * ENC + 2 * tx]      = ar0[i];
            *(unsigned long long*)&oxr[n * ENC + 32 + 2 * tx] = ar1[i];
        }
    }
}

// ---------------- fused score + softmax aggregation, both stacks ----------------
// Warp per node. Lanes 0-15: actor, lanes 16-31: critic.
// Within each half: two 8-lane edge groups (2 edges per warp iteration);
// each lane owns 8 dims. Score reduce = 3-level xor shuffle within the group.
// Softmax WITHOUT max subtraction (shift-invariant; scores are O(1)):
//   out[n] = (sum_e exp(s_e) * xl[src_e]) / (sum_e exp(s_e)) + bias
__global__ __launch_bounds__(256) void k_fused(int widx,
                                               const float* __restrict__ aatt,
                                               const float* __restrict__ catt,
                                               const float* __restrict__ ab,
                                               const float* __restrict__ cb,
                                               int out_sel, int do_relu) {
    int gw = (blockIdx.x * blockDim.x + threadIdx.x) >> 5;
    if (gw >= NN) return;
    int lane = threadIdx.x & 31;
    int half = lane >> 4;        // 0 = actor, 1 = critic
    int sub  = lane & 15;
    int grp  = sub >> 3;         // edge slot within half
    int l8   = sub & 7;          // dim group: owns dims d0..d0+7
    int d0   = l8 * 8;

    float* outP = half ? (out_sel ? g_hD : g_hC) : (out_sel ? g_hB : g_hA);
    const float* xlP = half ? g_xlC : g_xlA;
    const float* xrP = half ? g_xrC : g_xrA;
    const float* att = half ? catt : aatt;
    const float* bs  = half ? cb   : ab;
    int wbase = widx + half * 3;

    int beg = g_rowptr[gw];
    int deg = g_rowptr[gw + 1] - beg;

    if (deg == 0) {
        if (sub < 8) {
            float4 b0 = __ldg((const float4*)&bs[d0]);
            float4 b1 = __ldg((const float4*)&bs[d0 + 4]);
            if (do_relu) {
                b0.x = fmaxf(b0.x, 0.f); b0.y = fmaxf(b0.y, 0.f);
                b0.z = fmaxf(b0.z, 0.f); b0.w = fmaxf(b0.w, 0.f);
                b1.x = fmaxf(b1.x, 0.f); b1.y = fmaxf(b1.y, 0.f);
                b1.z = fmaxf(b1.z, 0.f); b1.w = fmaxf(b1.w, 0.f);
            }
            *(float4*)&outP[gw * ENC + d0]     = b0;
            *(float4*)&outP[gw * ENC + d0 + 4] = b1;
        }
        return;
    }

    // per-warp constants (loaded once per node)
    float w[4][8];
    const float* Wp = &g_Weff[wbase * 4 * ENC];
#pragma unroll
    for (int j = 0; j < 4; j++) {
        float4 wa = __ldg((const float4*)&Wp[j * ENC + d0]);
        float4 wb = __ldg((const float4*)&Wp[j * ENC + d0 + 4]);
        w[j][0] = wa.x; w[j][1] = wa.y; w[j][2] = wa.z; w[j][3] = wa.w;
        w[j][4] = wb.x; w[j][5] = wb.y; w[j][6] = wb.z; w[j][7] = wb.w;
    }
    float at[8];
    {
        float4 a0 = __ldg((const float4*)&att[d0]);
        float4 a1 = __ldg((const float4*)&att[d0 + 4]);
        at[0] = a0.x; at[1] = a0.y; at[2] = a0.z; at[3] = a0.w;
        at[4] = a1.x; at[5] = a1.y; at[6] = a1.z; at[7] = a1.w;
    }
    float xrb[8];   // xr[dst] + beff, folded per node
    {
        float4 x0 = *(const float4*)&xrP[gw * ENC + d0];
        float4 x1 = *(const float4*)&xrP[gw * ENC + d0 + 4];
        float4 e0 = __ldg((const float4*)&g_beff[wbase * ENC + d0]);
        float4 e1 = __ldg((const float4*)&g_beff[wbase * ENC + d0 + 4]);
        xrb[0] = x0.x + e0.x; xrb[1] = x0.y + e0.y; xrb[2] = x0.z + e0.z; xrb[3] = x0.w + e0.w;
        xrb[4] = x1.x + e1.x; xrb[5] = x1.y + e1.y; xrb[6] = x1.z + e1.z; xrb[7] = x1.w + e1.w;
    }

    float denom = 0.f;
    float acc[8];
#pragma unroll
    for (int d = 0; d < 8; d++) acc[d] = 0.f;

    int niter = (deg + 1) >> 1;
#pragma unroll 2
    for (int it = 0; it < niter; it++) {
        int j0 = 2 * it + grp;
        bool active = (j0 < deg);
        int e = beg + (active ? j0 : 0);
        int sidx = __ldg(&g_psrc[e]);
        float4 ev = __ldg(&g_pea[e]);
        float4 xa = *(const float4*)&xlP[sidx * ENC + d0];
        float4 xb = *(const float4*)&xlP[sidx * ENC + d0 + 4];
        float xl8[8] = {xa.x, xa.y, xa.z, xa.w, xb.x, xb.y, xb.z, xb.w};

        float part = 0.f;
#pragma unroll
        for (int d = 0; d < 8; d++) {
            float m = xl8[d] + xrb[d];
            m = fmaf(ev.x, w[0][d], m);
            m = fmaf(ev.y, w[1][d], m);
            m = fmaf(ev.z, w[2][d], m);
            m = fmaf(ev.w, w[3][d], m);
            float l = fmaxf(m, 0.f) + 0.2f * fminf(m, 0.f);
            part = fmaf(l, at[d], part);
        }
        // 3-level reduce within the 8-lane group (all lanes get the sum)
        part += __shfl_xor_sync(0xffffffffu, part, 1);
        part += __shfl_xor_sync(0xffffffffu, part, 2);
        part += __shfl_xor_sync(0xffffffffu, part, 4);

        float ex = active ? __expf(part) : 0.f;
        denom += ex;
#pragma unroll
        for (int d = 0; d < 8; d++) acc[d] = fmaf(ex, xl8[d], acc[d]);
    }

    // combine the two edge groups within each half (xor 8)
    denom += __shfl_xor_sync(0xffffffffu, denom, 8);
#pragma unroll
    for (int d = 0; d < 8; d++) acc[d] += __shfl_xor_sync(0xffffffffu, acc[d], 8);

    if (sub < 8) {
        float inv = 1.f / denom;
        float4 b0 = __ldg((const float4*)&bs[d0]);
        float4 b1 = __ldg((const float4*)&bs[d0 + 4]);
        float4 o0, o1;
        o0.x = fmaf(acc[0], inv, b0.x); o0.y = fmaf(acc[1], inv, b0.y);
        o0.z = fmaf(acc[2], inv, b0.z); o0.w = fmaf(acc[3], inv, b0.w);
        o1.x = fmaf(acc[4], inv, b1.x); o1.y = fmaf(acc[5], inv, b1.y);
        o1.z = fmaf(acc[6], inv, b1.z); o1.w = fmaf(acc[7], inv, b1.w);
        if (do_relu) {
            o0.x = fmaxf(o0.x, 0.f); o0.y = fmaxf(o0.y, 0.f);
            o0.z = fmaxf(o0.z, 0.f); o0.w = fmaxf(o0.w, 0.f);
            o1.x = fmaxf(o1.x, 0.f); o1.y = fmaxf(o1.y, 0.f);
            o1.z = fmaxf(o1.z, 0.f); o1.w = fmaxf(o1.w, 0.f);
        }
        *(float4*)&outP[gw * ENC + d0]     = o0;
        *(float4*)&outP[gw * ENC + d0 + 4] = o1;
    }
}

// ---------------- fused decoder: actions (tanh) from hA, value from hC ----------------
__global__ void k_decode(const float* __restrict__ Wa, const float* __restrict__ ba,
                         const float* __restrict__ Wv, const float* __restrict__ bv,
                         float* __restrict__ out) {
    __shared__ float sWa[ENC * OUTD];
    __shared__ float sWv[ENC];
    __shared__ float sba[OUTD];
    __shared__ float sbv;
    int tid = threadIdx.x;
    for (int i = tid; i < ENC * OUTD; i += blockDim.x) sWa[i] = Wa[i];
    for (int i = tid; i < ENC; i += blockDim.x) sWv[i] = Wv[i];
    if (tid < OUTD) sba[tid] = ba[tid];
    if (tid == 0) sbv = bv[0];
    __syncthreads();
    int n = blockIdx.x * blockDim.x + tid;
    if (n >= NN) return;
    float acc[OUTD];
#pragma unroll
    for (int c = 0; c < OUTD; c++) acc[c] = sba[c];
    float accv = sbv;
    const float* hA = &g_hA[n * ENC];   // actor final (round 2 writes hA)
    const float* hC = &g_hC[n * ENC];   // critic final (round 2 writes hC)
    for (int k = 0; k < ENC; k++) {
        float ha = hA[k];
#pragma unroll
        for (int c = 0; c < OUTD; c++) acc[c] = fmaf(ha, sWa[k * OUTD + c], acc[c]);
        accv = fmaf(hC[k], sWv[k], accv);
    }
#pragma unroll
    for (int c = 0; c < OUTD; c++) out[n * 6 + c] = tanhf(acc[c]);
    out[n * 6 + 5] = accv;
}

// ---------------- launcher ----------------
extern "C" void kernel_launch(void* const* d_in, const int* in_sizes, int n_in,
                              void* d_out, int out_size) {
    const float* x      = (const float*)d_in[0];
    const float* ea     = (const float*)d_in[1];
    const float* W_node = (const float*)d_in[2];
    const float* b_node = (const float*)d_in[3];
    const float* W_edge = (const float*)d_in[4];
    const float* b_edge = (const float*)d_in[5];
    const float* aWl    = (const float*)d_in[6];
    const float* aWr    = (const float*)d_in[7];
    const float* aWe    = (const float*)d_in[8];
    const float* aatt   = (const float*)d_in[9];
    const float* ab     = (const float*)d_in[10];
    const float* cWl    = (const float*)d_in[11];
    const float* cWr    = (const float*)d_in[12];
    const float* cWe    = (const float*)d_in[13];
    const float* catt   = (const float*)d_in[14];
    const float* cb     = (const float*)d_in[15];
    const float* W_act  = (const float*)d_in[16];
    const float* b_act  = (const float*)d_in[17];
    const float* W_val  = (const float*)d_in[18];
    const float* b_val  = (const float*)d_in[19];
    const int*   src    = (const int*)d_in[20];
    const int*   dst    = (const int*)d_in[21];
    float* out = (float*)d_out;

    // CSR build with src/edge_attr permutation
    k_zero_counts<<<(NN + 255) / 256, 256>>>();
    k_count<<<(NE + 255) / 256, 256>>>(dst);
    k_scan<<<1, 1024>>>();
    k_scatter<<<(NE + 255) / 256, 256>>>(dst, src, (const float4*)ea);

    // folded edge weights + node encoder
    k_weff<<<6, ENC>>>(W_edge, b_edge, aWe, cWe);
    k_node_enc<<<(NN + 255) / 256, 256>>>(x, W_node, b_node);

    int gemm_blocks  = (NN + 63) / 64;
    int fused_blocks = (NN * 32 + 255) / 256;   // warp per node

    // actor chain: h0 -> hA -> hB -> hA ; critic chain: h0 -> hC -> hD -> hC
    const int inA[3] = {0, 1, 2};
    const int inC[3] = {0, 3, 4};
    const int osel[3] = {0, 1, 0};

    for (int r = 0; r < 3; r++) {
        k_gemm<<<gemm_blocks, 256>>>(inA[r], 0, aWl + r * ENC * ENC, aWr + r * ENC * ENC);
        k_gemm<<<gemm_blocks, 256>>>(inC[r], 1, cWl + r * ENC * ENC, cWr + r * ENC * ENC);
        k_fused<<<fused_blocks, 256>>>(r, aatt + r * ENC, catt + r * ENC,
                                       ab + r * ENC, cb + r * ENC,
                                       osel[r], (r < 2) ? 1 : 0);
    }

    k_decode<<<(NN + 255) / 256, 256>>>(W_act, b_act, W_val, b_val, out);
}